// round 8
// baseline (speedup 1.0000x reference)
#include <cuda_runtime.h>
#include <cuda_bf16.h>

// Problem sizes (fixed by the dataset): 1,000,000 nodes, 2,000,000 elements.
#define MAX_NODES 1000000

__device__ float  g_uphys4[4 * MAX_NODES];
__device__ float  g_fint4 [4 * MAX_NODES];
__device__ double g_sums[2];     // [0] = sum(R_free^2), [1] = sum(F_free^2)
__device__ int    g_conn_is64;   // 1 if connectivity is int64, 0 if int32
__device__ unsigned int g_done_count;   // last-block counter (reset by last block)

__device__ __forceinline__ void red_add_v4(float* addr, float x, float y, float z, float w)
{
    asm volatile("red.global.add.v4.f32 [%0], {%1, %2, %3, %4};"
                 :: "l"(addr), "f"(x), "f"(y), "f"(z), "f"(w) : "memory");
}

// -------- Kernel 1: dtype probe (block 0) + u_phys4 scale + F_int4 zero -----
__global__ void prep_kernel(const float* __restrict__ pred_raw,
                            const float* __restrict__ u_c,
                            const float* __restrict__ theta_c,
                            const unsigned int* __restrict__ conn_w,
                            int conn_words,
                            int n_nodes)
{
    if (blockIdx.x == 0) {
        __shared__ unsigned int acc;
        if (threadIdx.x == 0) { acc = 0u; g_sums[0] = 0.0; g_sums[1] = 0.0; }
        __syncthreads();
        unsigned int v = 0u;
        int lim = conn_words < 8192 ? conn_words : 8192;
        for (int i = 2 * threadIdx.x + 1; i < lim; i += 2 * blockDim.x)
            v |= conn_w[i];
        atomicOr(&acc, v);
        __syncthreads();
        if (threadIdx.x == 0) g_conn_is64 = (acc == 0u) ? 1 : 0;
    }
    float uc = u_c[0];
    float tc = theta_c[0];
    int i = blockIdx.x * blockDim.x + threadIdx.x;
    if (i >= n_nodes) return;
    float px = pred_raw[3 * i + 0];
    float py = pred_raw[3 * i + 1];
    float pz = pred_raw[3 * i + 2];
    reinterpret_cast<float4*>(g_uphys4)[i] = make_float4(px * uc, py * uc, pz * tc, 0.0f);
    reinterpret_cast<float4*>(g_fint4 )[i] = make_float4(0.0f, 0.0f, 0.0f, 0.0f);
}

// Per-element force computation + scatter (shared by main path and tail).
__device__ __forceinline__ void elem_body(long long nA, long long nB,
                                          float4 uA, float4 uB,
                                          float l, float Ee, float Av, float Iv,
                                          float c, float s)
{
    float inv_l = 1.0f / l;
    float ea_l  = Ee * Av * inv_l;
    float ei_l  = Ee * Iv * inv_l;
    float ei_l2 = ei_l * inv_l;
    float ei_l3 = ei_l2 * inv_l;

    float d0 =  c * uA.x + s * uA.y;
    float d1 = -s * uA.x + c * uA.y;
    float d2v = -uA.z;
    float d3 =  c * uB.x + s * uB.y;
    float d4 = -s * uB.x + c * uB.y;
    float d5 = -uB.z;

    float du = d0 - d3;
    float dw = d1 - d4;
    float f0 = ea_l * du;
    float f1 = 12.0f * ei_l3 * dw + 6.0f * ei_l2 * (d2v + d5);
    float f2 =  6.0f * ei_l2 * dw + ei_l * (4.0f * d2v + 2.0f * d5);
    float f5 =  6.0f * ei_l2 * dw + ei_l * (2.0f * d2v + 4.0f * d5);

    float gAx = c * f0 - s * f1;
    float gAy = s * f0 + c * f1;

    red_add_v4(&g_fint4[4 * nA],  gAx,  gAy, -f2, 0.0f);
    red_add_v4(&g_fint4[4 * nB], -gAx, -gAy, -f5, 0.0f);
}

// -------- Kernel 2: element forces, 4 elements per thread -------------------
__global__ void elem_kernel(const void* __restrict__ conn_raw,
                            const float* __restrict__ L,
                            const float* __restrict__ E,
                            const float* __restrict__ A,
                            const float* __restrict__ I22,
                            const float* __restrict__ dirs,       // (E,3)
                            int n_elem, int n_nodes)
{
    int p  = blockIdx.x * blockDim.x + threadIdx.x;   // quad-of-elements index
    int e0 = 4 * p;
    if (e0 >= n_elem) return;

    if (e0 + 3 < n_elem) {
        // ---- indices: 4 elements ----
        long long nA[4], nB[4];
        if (g_conn_is64) {
            const longlong2* cp = reinterpret_cast<const longlong2*>((const long long*)conn_raw);
#pragma unroll
            for (int k = 0; k < 4; k++) { longlong2 cc = cp[e0 + k]; nA[k] = cc.x; nB[k] = cc.y; }
        } else {
            const int4* cp = reinterpret_cast<const int4*>((const int*)conn_raw);
            int4 c01 = cp[2 * p + 0];
            int4 c23 = cp[2 * p + 1];
            nA[0] = c01.x; nB[0] = c01.y; nA[1] = c01.z; nB[1] = c01.w;
            nA[2] = c23.x; nB[2] = c23.y; nA[3] = c23.z; nB[3] = c23.w;
        }
#pragma unroll
        for (int k = 0; k < 4; k++) {
            if ((unsigned long long)nA[k] >= (unsigned long long)n_nodes) nA[k] = 0;
            if ((unsigned long long)nB[k] >= (unsigned long long)n_nodes) nB[k] = 0;
        }

        // ---- issue all 8 random gathers up front ----
        const float4* up4 = reinterpret_cast<const float4*>(g_uphys4);
        float4 uA[4], uB[4];
#pragma unroll
        for (int k = 0; k < 4; k++) { uA[k] = up4[nA[k]]; uB[k] = up4[nB[k]]; }

        // ---- streamed properties: pure LDG.128 ----
        float4 lv = reinterpret_cast<const float4*>(L  )[p];
        float4 ev = reinterpret_cast<const float4*>(E  )[p];
        float4 av = reinterpret_cast<const float4*>(A  )[p];
        float4 iv = reinterpret_cast<const float4*>(I22)[p];
        const float4* d4p = reinterpret_cast<const float4*>(dirs + 12 * p);
        float4 v0 = d4p[0];   // c0, -, s0, c1
        float4 v1 = d4p[1];   // -, s1, c2, -
        float4 v2 = d4p[2];   // s2, c3, -, s3

        elem_body(nA[0], nB[0], uA[0], uB[0], lv.x, ev.x, av.x, iv.x, v0.x, v0.z);
        elem_body(nA[1], nB[1], uA[1], uB[1], lv.y, ev.y, av.y, iv.y, v0.w, v1.y);
        elem_body(nA[2], nB[2], uA[2], uB[2], lv.z, ev.z, av.z, iv.z, v1.z, v2.x);
        elem_body(nA[3], nB[3], uA[3], uB[3], lv.w, ev.w, av.w, iv.w, v2.y, v2.w);
    } else {
        // tail: scalar per element
        for (int e = e0; e < n_elem; e++) {
            long long nA, nB;
            if (g_conn_is64) {
                longlong2 cc = reinterpret_cast<const longlong2*>((const long long*)conn_raw)[e];
                nA = cc.x; nB = cc.y;
            } else {
                int2 cc = reinterpret_cast<const int2*>((const int*)conn_raw)[e];
                nA = cc.x; nB = cc.y;
            }
            if ((unsigned long long)nA >= (unsigned long long)n_nodes) nA = 0;
            if ((unsigned long long)nB >= (unsigned long long)n_nodes) nB = 0;
            float4 uA = reinterpret_cast<const float4*>(g_uphys4)[nA];
            float4 uB = reinterpret_cast<const float4*>(g_uphys4)[nB];
            elem_body(nA, nB, uA, uB, L[e], E[e], A[e], I22[e],
                      dirs[3 * e + 0], dirs[3 * e + 2]);
        }
    }
}

// -------- Kernel 3: masked residual sums (8 nodes/thread) + finalize --------
__global__ void reduce_kernel(const float* __restrict__ F_ext,
                              const int*   __restrict__ bc_disp,
                              const int*   __restrict__ bc_rot,
                              int n_nodes,
                              float* __restrict__ out)
{
    float sRf = 0.0f, sFf = 0.0f;
    int q  = blockIdx.x * blockDim.x + threadIdx.x;   // oct index
    int i0 = 8 * q;
    const float4* fi4 = reinterpret_cast<const float4*>(g_fint4);

    if (i0 + 7 < n_nodes) {
        float fl[32];
        float fe[24];
        int   bdv[8], brv[8];
#pragma unroll
        for (int k = 0; k < 8; k++) {
            float4 t = fi4[i0 + k];
            fl[4*k+0] = t.x; fl[4*k+1] = t.y; fl[4*k+2] = t.z; fl[4*k+3] = t.w;
        }
        {
            const float4* fe4 = reinterpret_cast<const float4*>(F_ext + 3 * i0);
#pragma unroll
            for (int k = 0; k < 6; k++) {
                float4 t = fe4[k];
                fe[4*k+0] = t.x; fe[4*k+1] = t.y; fe[4*k+2] = t.z; fe[4*k+3] = t.w;
            }
            int4 b0 = reinterpret_cast<const int4*>(bc_disp)[2*q+0];
            int4 b1 = reinterpret_cast<const int4*>(bc_disp)[2*q+1];
            bdv[0]=b0.x; bdv[1]=b0.y; bdv[2]=b0.z; bdv[3]=b0.w;
            bdv[4]=b1.x; bdv[5]=b1.y; bdv[6]=b1.z; bdv[7]=b1.w;
            int4 r0 = reinterpret_cast<const int4*>(bc_rot)[2*q+0];
            int4 r1 = reinterpret_cast<const int4*>(bc_rot)[2*q+1];
            brv[0]=r0.x; brv[1]=r0.y; brv[2]=r0.z; brv[3]=r0.w;
            brv[4]=r1.x; brv[5]=r1.y; brv[6]=r1.z; brv[7]=r1.w;
        }
#pragma unroll
        for (int j = 0; j < 8; j++) {
            float fd = 1.0f - (float)bdv[j];
            float fr = 1.0f - (float)brv[j];
            float fx = fe[3*j+0], fy = fe[3*j+1], fz = fe[3*j+2];
            float rx = (fl[4*j+0] - fx) * fd;
            float ry = (fl[4*j+1] - fy) * fd;
            float rz = (fl[4*j+2] - fz) * fr;
            float gx = fx * fd, gy = fy * fd, gz = fz * fr;
            sRf += rx*rx + ry*ry + rz*rz;
            sFf += gx*gx + gy*gy + gz*gz;
        }
    } else {
        for (int i = i0; i < n_nodes; i++) {
            float4 fi = fi4[i];
            float fd = 1.0f - (float)bc_disp[i];
            float fr = 1.0f - (float)bc_rot[i];
            float fx = F_ext[3 * i + 0];
            float fy = F_ext[3 * i + 1];
            float fz = F_ext[3 * i + 2];
            float rx = (fi.x - fx) * fd;
            float ry = (fi.y - fy) * fd;
            float rz = (fi.z - fz) * fr;
            float gx = fx * fd, gy = fy * fd, gz = fz * fr;
            sRf += rx*rx + ry*ry + rz*rz;
            sFf += gx*gx + gy*gy + gz*gz;
        }
    }

    double sR = (double)sRf;
    double sF = (double)sFf;
    for (int off = 16; off > 0; off >>= 1) {
        sR += __shfl_down_sync(0xFFFFFFFFu, sR, off);
        sF += __shfl_down_sync(0xFFFFFFFFu, sF, off);
    }
    __shared__ double shR[8], shF[8];
    __shared__ bool   is_last;
    int lane = threadIdx.x & 31;
    int wid  = threadIdx.x >> 5;
    if (lane == 0) { shR[wid] = sR; shF[wid] = sF; }
    __syncthreads();
    if (wid == 0) {
        int nw = (blockDim.x + 31) >> 5;
        sR = (lane < nw) ? shR[lane] : 0.0;
        sF = (lane < nw) ? shF[lane] : 0.0;
        for (int off = 4; off > 0; off >>= 1) {
            sR += __shfl_down_sync(0xFFFFFFFFu, sR, off);
            sF += __shfl_down_sync(0xFFFFFFFFu, sF, off);
        }
        if (lane == 0) {
            atomicAdd(&g_sums[0], sR);
            atomicAdd(&g_sums[1], sF);
            __threadfence();
            unsigned int prev = atomicAdd(&g_done_count, 1u);
            is_last = (prev == gridDim.x - 1);
        }
    }
    __syncthreads();
    if (is_last && threadIdx.x == 0) {
        g_done_count = 0;   // reset for the next call
        double denom = g_sums[1];
        if (denom < 1e-30) denom = 1e-30;
        out[0] = (float)(g_sums[0] / denom);
    }
}

extern "C" void kernel_launch(void* const* d_in, const int* in_sizes, int n_in,
                              void* d_out, int out_size)
{
    const float* pred_raw = (const float*)d_in[0];   // (N,3)
    const float* u_c      = (const float*)d_in[1];   // (1,)
    const float* theta_c  = (const float*)d_in[2];   // (1,)
    const void*  conn     =                d_in[3];  // (E,2) int32 or int64
    const float* L        = (const float*)d_in[4];   // (E,)
    const float* E        = (const float*)d_in[5];
    const float* A        = (const float*)d_in[6];
    const float* I22      = (const float*)d_in[7];
    const float* dirs     = (const float*)d_in[8];   // (E,3)
    const float* F_ext    = (const float*)d_in[9];   // (N,3)
    const int*   bc_disp  = (const int*)  d_in[10];  // (N,1)
    const int*   bc_rot   = (const int*)  d_in[11];  // (N,1)
    float*       out      = (float*)d_out;

    int n_nodes = in_sizes[0] / 3;
    int n_elem  = in_sizes[4];

    const int T = 256;
    prep_kernel<<<(n_nodes + T - 1) / T, T>>>(pred_raw, u_c, theta_c,
                                              (const unsigned int*)conn,
                                              2 * n_elem, n_nodes);
    {
        int n_quads = (n_elem + 3) / 4;
        elem_kernel<<<(n_quads + T - 1) / T, T>>>(conn, L, E, A, I22, dirs,
                                                  n_elem, n_nodes);
    }
    {
        int n_octs = (n_nodes + 7) / 8;
        reduce_kernel<<<(n_octs + T - 1) / T, T>>>(F_ext, bc_disp, bc_rot,
                                                   n_nodes, out);
    }
}